// round 1
// baseline (speedup 1.0000x reference)
#include <cuda_runtime.h>
#include <cstdint>

// Problem dimensions (fixed by the dataset)
#define NNODES 8000
#define NEDGES 32000
#define NBATCH 64
#define DEMB   200
#define TTOK   20
#define F0     4000   // embed width = conv1 in
#define F1     6000   // conv1/conv2 out
#define F3     3000   // lin1 out
#define F4     4      // lin2 out

// -------- scratch (device globals; no allocation in kernel_launch) --------
__device__ float    g_h0 [(size_t)NNODES * F0];   // embedded features
__device__ float    g_xw [(size_t)NNODES * F1];   // xw1 / later agg2+h2
__device__ float    g_agg[(size_t)NNODES * F1];   // agg1 -> h1
__device__ float    g_xw2[(size_t)NNODES * F1];   // xw2
__device__ float    g_deg [NNODES];
__device__ float    g_dinv[NNODES];
__device__ unsigned g_gmax[(size_t)NBATCH * F1];
__device__ float    g_g   [(size_t)NBATCH * F1];
__device__ float    g_g1  [(size_t)NBATCH * F3];

__device__ __forceinline__ float leaky(float v) { return v >= 0.0f ? v : 0.01f * v; }

// monotone float <-> uint encoding for atomicMax on floats
__device__ __forceinline__ unsigned fenc(float f) {
    unsigned u = __float_as_uint(f);
    return (u & 0x80000000u) ? ~u : (u | 0x80000000u);
}
__device__ __forceinline__ float fdec(unsigned u) {
    return (u & 0x80000000u) ? __uint_as_float(u ^ 0x80000000u) : __uint_as_float(~u);
}

// -------- embedding gather: h0[n, t*200+d] = emb[x[n,t], d] --------
__global__ void k_embed(const int* __restrict__ x, const float* __restrict__ emb) {
    int n  = blockIdx.y;
    int j4 = blockIdx.x * blockDim.x + threadIdx.x;   // 0..999
    if (j4 >= F0 / 4) return;
    int col = j4 * 4;
    int t = col / DEMB;
    int d = col % DEMB;
    int tok = x[n * TTOK + t];
    float4 v = *(const float4*)(emb + (size_t)tok * DEMB + d);
    *(float4*)(g_h0 + (size_t)n * F0 + col) = v;
}

// -------- degree / dinv --------
__global__ void k_deg_init() {
    int n = blockIdx.x * blockDim.x + threadIdx.x;
    if (n < NNODES) g_deg[n] = 1.0f;   // self-loop
}
__global__ void k_deg_count(const int* __restrict__ dst) {
    int e = blockIdx.x * blockDim.x + threadIdx.x;
    if (e < NEDGES) atomicAdd(&g_deg[dst[e]], 1.0f);
}
__global__ void k_dinv() {
    int n = blockIdx.x * blockDim.x + threadIdx.x;
    if (n < NNODES) g_dinv[n] = rsqrtf(g_deg[n]);
}

// -------- SGEMM: C = A[MxK] * B[KxN]; epi==1 adds bias + leaky_relu --------
// 128x128 block tile, 8x8 microtile, BK=8, 256 threads.
__global__ void __launch_bounds__(256) k_sgemm(
    const float* __restrict__ A, const float* __restrict__ B,
    const float* __restrict__ bias, float* __restrict__ C,
    int M, int N, int K, int epi)
{
    __shared__ float As[8][128];
    __shared__ float Bs[8][128];

    int tid = threadIdx.x;
    int tx  = tid & 15;        // col group
    int ty  = tid >> 4;        // row group
    int bx  = blockIdx.x;      // N tiles
    int by  = blockIdx.y;      // M tiles

    int aRow = tid >> 1;            // 0..127
    int aCol = (tid & 1) * 4;       // 0 or 4
    int bRow = tid >> 5;            // 0..7
    int bCol = (tid & 31) * 4;      // 0..124

    bool aValid = (by * 128 + aRow) < M;
    bool bValid = (bx * 128 + bCol) < N;   // N%4==0 => all-or-nothing float4

    const float* Aptr = A + (size_t)(by * 128 + aRow) * K + aCol;
    const float* Bptr = B + (size_t)bRow * N + bx * 128 + bCol;

    float4 av = aValid ? *(const float4*)Aptr : make_float4(0.f, 0.f, 0.f, 0.f);
    float4 bv = bValid ? *(const float4*)Bptr : make_float4(0.f, 0.f, 0.f, 0.f);

    float acc[8][8];
    #pragma unroll
    for (int i = 0; i < 8; i++)
        #pragma unroll
        for (int j = 0; j < 8; j++) acc[i][j] = 0.0f;

    for (int k0 = 0; k0 < K; k0 += 8) {
        As[aCol + 0][aRow] = av.x;
        As[aCol + 1][aRow] = av.y;
        As[aCol + 2][aRow] = av.z;
        As[aCol + 3][aRow] = av.w;
        *(float4*)&Bs[bRow][bCol] = bv;
        __syncthreads();

        if (k0 + 8 < K) {
            av = aValid ? *(const float4*)(Aptr + k0 + 8) : make_float4(0.f, 0.f, 0.f, 0.f);
            bv = bValid ? *(const float4*)(Bptr + (size_t)(k0 + 8) * N) : make_float4(0.f, 0.f, 0.f, 0.f);
        }

        #pragma unroll
        for (int k = 0; k < 8; k++) {
            float ar[8], br[8];
            #pragma unroll
            for (int i = 0; i < 8; i++) ar[i] = As[k][ty * 8 + i];
            #pragma unroll
            for (int j = 0; j < 8; j++) br[j] = Bs[k][tx * 8 + j];
            #pragma unroll
            for (int i = 0; i < 8; i++)
                #pragma unroll
                for (int j = 0; j < 8; j++)
                    acc[i][j] = fmaf(ar[i], br[j], acc[i][j]);
        }
        __syncthreads();
    }

    int row0 = by * 128 + ty * 8;
    int col0 = bx * 128 + tx * 8;
    #pragma unroll
    for (int i = 0; i < 8; i++) {
        int r = row0 + i;
        if (r >= M) break;
        #pragma unroll
        for (int j = 0; j < 8; j++) {
            int c = col0 + j;
            if (c < N) {
                float v = acc[i][j];
                if (epi == 1) v = leaky(v + bias[c]);
                C[(size_t)r * N + c] = v;
            }
        }
    }
}

// -------- aggregation: self-loop init, edge atomics, bias+leaky finalize ----
__global__ void k_agg_init(const float* __restrict__ xw, float* __restrict__ agg) {
    int n  = blockIdx.y;
    int j4 = blockIdx.x * blockDim.x + threadIdx.x;
    if (j4 >= F1 / 4) return;
    float di = g_dinv[n];
    float s  = di * di;
    float4 v = *(const float4*)(xw + (size_t)n * F1 + j4 * 4);
    v.x *= s; v.y *= s; v.z *= s; v.w *= s;
    *(float4*)(agg + (size_t)n * F1 + j4 * 4) = v;
}

__global__ void k_agg_edges(const float* __restrict__ xw, float* __restrict__ agg,
                            const int* __restrict__ src, const int* __restrict__ dst) {
    int e  = blockIdx.y;
    int j4 = blockIdx.x * blockDim.x + threadIdx.x;
    if (j4 >= F1 / 4) return;
    int s = __ldg(&src[e]);
    int d = __ldg(&dst[e]);
    float nrm = g_dinv[s] * g_dinv[d];
    float4 v = *(const float4*)(xw + (size_t)s * F1 + j4 * 4);
    float* o = agg + (size_t)d * F1 + j4 * 4;
    atomicAdd(o + 0, v.x * nrm);
    atomicAdd(o + 1, v.y * nrm);
    atomicAdd(o + 2, v.z * nrm);
    atomicAdd(o + 3, v.w * nrm);
}

__global__ void k_bias_leaky(float* __restrict__ h, const float* __restrict__ b) {
    int n  = blockIdx.y;
    int j4 = blockIdx.x * blockDim.x + threadIdx.x;
    if (j4 >= F1 / 4) return;
    int c = j4 * 4;
    float4 v  = *(float4*)(h + (size_t)n * F1 + c);
    float4 bb = *(const float4*)(b + c);
    v.x = leaky(v.x + bb.x);
    v.y = leaky(v.y + bb.y);
    v.z = leaky(v.z + bb.z);
    v.w = leaky(v.w + bb.w);
    *(float4*)(h + (size_t)n * F1 + c) = v;
}

// -------- global max pool (segment_max over sorted batch) --------
__global__ void k_gmax_init() {
    int b  = blockIdx.y;
    int j4 = blockIdx.x * blockDim.x + threadIdx.x;
    if (j4 >= F1 / 4) return;
    unsigned enc_ninf = 0x007FFFFFu;   // fenc(-inf)
    uint4 v = make_uint4(enc_ninf, enc_ninf, enc_ninf, enc_ninf);
    *(uint4*)(g_gmax + (size_t)b * F1 + j4 * 4) = v;
}

__global__ void k_gmax(const float* __restrict__ h2, const int* __restrict__ batch) {
    int n  = blockIdx.y;
    int j4 = blockIdx.x * blockDim.x + threadIdx.x;
    if (j4 >= F1 / 4) return;
    int b = __ldg(&batch[n]);
    int c = j4 * 4;
    float4 v = *(const float4*)(h2 + (size_t)n * F1 + c);
    unsigned* o = g_gmax + (size_t)b * F1 + c;
    atomicMax(o + 0, fenc(v.x));
    atomicMax(o + 1, fenc(v.y));
    atomicMax(o + 2, fenc(v.z));
    atomicMax(o + 3, fenc(v.w));
}

__global__ void k_gmax_dec() {
    int b  = blockIdx.y;
    int j4 = blockIdx.x * blockDim.x + threadIdx.x;
    if (j4 >= F1 / 4) return;
    int c = j4 * 4;
    uint4 u = *(const uint4*)(g_gmax + (size_t)b * F1 + c);
    float4 v = make_float4(fdec(u.x), fdec(u.y), fdec(u.z), fdec(u.w));
    *(float4*)(g_g + (size_t)b * F1 + c) = v;
}

// -------- final tiny GEMM: out = leaky(g1 @ Wl2 + bl2), one warp per output --
__global__ void k_final(const float* __restrict__ g1, const float* __restrict__ Wl2,
                        const float* __restrict__ bl2, float* __restrict__ out) {
    int gwarp = (blockIdx.x * blockDim.x + threadIdx.x) >> 5;   // 0..255
    int lane  = threadIdx.x & 31;
    if (gwarp >= NBATCH * F4) return;
    int m = gwarp >> 2;
    int n = gwarp & 3;
    float acc = 0.0f;
    for (int k = lane; k < F3; k += 32)
        acc = fmaf(g1[(size_t)m * F3 + k], Wl2[(size_t)k * F4 + n], acc);
    #pragma unroll
    for (int o = 16; o > 0; o >>= 1)
        acc += __shfl_xor_sync(0xFFFFFFFFu, acc, o);
    if (lane == 0) out[m * F4 + n] = leaky(acc + bl2[n]);
}

// --------------------------------------------------------------------------
extern "C" void kernel_launch(void* const* d_in, const int* in_sizes, int n_in,
                              void* d_out, int out_size) {
    const int*   x    = (const int*)d_in[0];
    const int*   ei   = (const int*)d_in[1];
    const int*   batch= (const int*)d_in[2];
    const float* emb  = (const float*)d_in[3];
    const float* W1   = (const float*)d_in[4];
    const float* b1   = (const float*)d_in[5];
    const float* W2   = (const float*)d_in[6];
    const float* b2   = (const float*)d_in[7];
    const float* Wl1  = (const float*)d_in[8];
    const float* bl1  = (const float*)d_in[9];
    const float* Wl2  = (const float*)d_in[10];
    const float* bl2  = (const float*)d_in[11];
    float* out = (float*)d_out;

    const int* srcp = ei;            // edge_index[0]
    const int* dstp = ei + NEDGES;   // edge_index[1]

    float *h0, *xw, *agg, *xw2, *gg, *g1;
    cudaGetSymbolAddress((void**)&h0,  g_h0);
    cudaGetSymbolAddress((void**)&xw,  g_xw);
    cudaGetSymbolAddress((void**)&agg, g_agg);
    cudaGetSymbolAddress((void**)&xw2, g_xw2);
    cudaGetSymbolAddress((void**)&gg,  g_g);
    cudaGetSymbolAddress((void**)&g1,  g_g1);

    dim3 blk(256);
    dim3 gEmbed(4, NNODES);                 // 4*256 >= 1000 float4/node
    dim3 gNode6k(6, NNODES);                // 6*256 >= 1500 float4/node
    dim3 gEdge6k(6, NEDGES);
    dim3 gB6k(6, NBATCH);
    dim3 gGemmBig(47, 63);                  // ceil(6000/128) x ceil(8000/128)
    dim3 gGemm3(24, 1);                     // ceil(3000/128) x ceil(64/128)

    // 1. embedding
    k_embed<<<gEmbed, blk>>>(x, emb);
    // 2. degrees (with self-loop) -> dinv
    k_deg_init <<<32, 256>>>();
    k_deg_count<<<(NEDGES + 255) / 256, 256>>>(dstp);
    k_dinv     <<<32, 256>>>();
    // 3. conv1: xw = h0 @ W1
    k_sgemm<<<gGemmBig, blk>>>(h0, W1, nullptr, xw, NNODES, F1, F0, 0);
    // 4. agg1 = D^-1/2 (A+I) D^-1/2 xw ; h1 = leaky(agg1 + b1) (in place in g_agg)
    k_agg_init <<<gNode6k, blk>>>(xw, agg);
    k_agg_edges<<<gEdge6k, blk>>>(xw, agg, srcp, dstp);
    k_bias_leaky<<<gNode6k, blk>>>(agg, b1);
    // 5. conv2: xw2 = h1 @ W2
    k_sgemm<<<gGemmBig, blk>>>(agg, W2, nullptr, xw2, NNODES, F1, F1, 0);
    // 6. agg2 (reuse g_xw) ; h2 = leaky(agg2 + b2)
    k_agg_init <<<gNode6k, blk>>>(xw2, xw);
    k_agg_edges<<<gEdge6k, blk>>>(xw2, xw, srcp, dstp);
    k_bias_leaky<<<gNode6k, blk>>>(xw, b2);
    // 7. global max pool -> g [64, 6000]
    k_gmax_init<<<gB6k, blk>>>();
    k_gmax     <<<gNode6k, blk>>>(xw, batch);
    k_gmax_dec <<<gB6k, blk>>>();
    // 8. lin1: g1 = leaky(g @ Wl1 + bl1)
    k_sgemm<<<gGemm3, blk>>>(gg, Wl1, bl1, g1, NBATCH, F3, F1, 1);
    // 9. lin2: out = leaky(g1 @ Wl2 + bl2)
    k_final<<<32, 256>>>(g1, Wl2, bl2, out);
}

// round 4
// speedup vs baseline: 1.3863x; 1.3863x over previous
#include <cuda_runtime.h>
#include <cstdint>
#include <cstddef>

// Problem dimensions (fixed by the dataset)
#define NNODES 8000
#define NEDGES 32000
#define NBATCH 64
#define DEMB   200
#define TTOK   20
#define F0     4000   // embed width = conv1 in
#define F1     6000   // conv1/conv2 out
#define F3     3000   // lin1 out
#define F4     4      // lin2 out

// -------- scratch (device globals; no allocation in kernel_launch) --------
__device__ __align__(1024) float    g_h0 [(size_t)NNODES * F0];
__device__ __align__(1024) float    g_xw [(size_t)NNODES * F1];
__device__ __align__(1024) float    g_agg[(size_t)NNODES * F1];
__device__ __align__(1024) float    g_xw2[(size_t)NNODES * F1];
__device__ __align__(1024) float    g_deg [NNODES];
__device__ __align__(1024) float    g_dinv[NNODES];
__device__ __align__(1024) unsigned g_gmax[(size_t)NBATCH * F1];
__device__ __align__(1024) float    g_g   [(size_t)NBATCH * F1];
__device__ __align__(1024) float    g_g1  [(size_t)NBATCH * F3];

__device__ __forceinline__ float leaky(float v) { return v >= 0.0f ? v : 0.01f * v; }

__device__ __forceinline__ unsigned fenc(float f) {
    unsigned u = __float_as_uint(f);
    return (u & 0x80000000u) ? ~u : (u | 0x80000000u);
}
__device__ __forceinline__ float fdec(unsigned u) {
    return (u & 0x80000000u) ? __uint_as_float(u ^ 0x80000000u) : __uint_as_float(~u);
}

// ===================== tf32 mma.sync GEMM with 3xTF32 compensation ================
// C[M,N] = A[M,K] @ B[K,N] ; A row-major, B row-major. Optional bias + leaky epilogue.
// Block tile 128x128, BK=32, 8 warps (2x4), warp tile 64x32, m16n8k8 tf32.
// Each fp32 operand split exactly: hi = x & 0xFFFFE000, lo = x - hi.
// D += Ah*Bh + Ah*Bl + Al*Bh  (al*bl dropped: ~2^-24 relative). fp32-quality result.
// 3-stage cp.async pipeline.

#define BM 128
#define BN 128
#define BK 32
#define ASTR 36      // As row stride (floats), padded
#define BSTR 132     // Bs row stride (floats), padded
#define A_TILE_F (BM * ASTR)
#define B_TILE_F (BK * BSTR)
#define NSTAGE 3
#define MM_SMEM (NSTAGE * (A_TILE_F + B_TILE_F) * 4)   // 105984 bytes

__device__ __forceinline__ void cp16z(uint32_t dst, const void* src, uint32_t srcsize) {
    asm volatile("cp.async.cg.shared.global [%0], [%1], 16, %2;"
                 :: "r"(dst), "l"(src), "r"(srcsize));
}
__device__ __forceinline__ uint32_t smem_u32(const void* p) {
    uint32_t a;
    asm("{ .reg .u64 t; cvta.to.shared.u64 t, %1; cvt.u32.u64 %0, t; }" : "=r"(a) : "l"(p));
    return a;
}
__device__ __forceinline__ void split32(float x, uint32_t& hi, uint32_t& lo) {
    uint32_t h = __float_as_uint(x) & 0xFFFFE000u;
    hi = h;
    lo = __float_as_uint(x - __uint_as_float(h));   // exact
}

#define MMA_TF32(ACC, AF, BF)                                                      \
    asm volatile(                                                                  \
        "mma.sync.aligned.m16n8k8.row.col.f32.tf32.tf32.f32 "                      \
        "{%0,%1,%2,%3}, {%4,%5,%6,%7}, {%8,%9}, {%0,%1,%2,%3};"                    \
        : "+f"((ACC)[0]), "+f"((ACC)[1]), "+f"((ACC)[2]), "+f"((ACC)[3])           \
        : "r"((AF)[0]), "r"((AF)[1]), "r"((AF)[2]), "r"((AF)[3]),                  \
          "r"((BF)[0]), "r"((BF)[1]))

__global__ void __launch_bounds__(256, 1)
k_mma(const float* __restrict__ A, const float* __restrict__ B,
      const float* __restrict__ bias, float* __restrict__ C,
      int M, int N, int K)
{
    extern __shared__ __align__(16) float smem[];
    const uint32_t sb = smem_u32(smem);

    const int tid  = threadIdx.x;
    const int wid  = tid >> 5;
    const int lane = tid & 31;
    const int g    = lane >> 2;   // group id 0..7
    const int t    = lane & 3;    // thread in group 0..3
    const int wm   = wid >> 2;    // 0..1
    const int wn   = wid & 3;     // 0..3

    const int m0 = blockIdx.y * BM;
    const int n0 = blockIdx.x * BN;
    const int KT = (K + BK - 1) / BK;

    // ---- global load mapping ----
    const int aRow  = tid >> 1;
    const int aColF = (tid & 1) * 16;
    int aRowG = m0 + aRow; if (aRowG > M - 1) aRowG = M - 1;
    const float* aSrcBase = A + (size_t)aRowG * K + aColF;
    const uint32_t aDstBase = sb + (uint32_t)(aRow * ASTR + aColF) * 4u;

    const int bRow  = tid >> 3;              // 0..31 (k within tile)
    const int bColF = (tid & 7) * 16;        // 0..112 (n within tile)
    const uint32_t bDstBase = sb + (uint32_t)(NSTAGE * A_TILE_F) * 4u
                                 + (uint32_t)(bRow * BSTR + bColF) * 4u;

    float acc[4][4][4];
    #pragma unroll
    for (int i = 0; i < 4; i++)
        #pragma unroll
        for (int j = 0; j < 4; j++)
            #pragma unroll
            for (int r = 0; r < 4; r++) acc[i][j][r] = 0.0f;

    auto load_tile = [&](int stage, int kt) {
        const int k0 = kt * BK;
        const uint32_t aDst = aDstBase + (uint32_t)(stage * A_TILE_F) * 4u;
        const uint32_t bDst = bDstBase + (uint32_t)(stage * B_TILE_F) * 4u;
        #pragma unroll
        for (int i = 0; i < 4; i++) {
            int kA = k0 + aColF + 4 * i;
            uint32_t sz = (kA + 4 <= K) ? 16u : 0u;
            cp16z(aDst + 16u * i, aSrcBase + (size_t)k0 + 4 * i, sz);
        }
        {
            const int kB = k0 + bRow;
            const bool krow_ok = (kB < K);
            const float* rowp = B + (size_t)(krow_ok ? kB : 0) * N;
            #pragma unroll
            for (int i = 0; i < 4; i++) {
                int col = n0 + bColF + 4 * i;                 // global N col of chunk
                // all N here are multiples of 4 => chunk fully in or fully out
                uint32_t sz = (krow_ok && (col + 4 <= N)) ? 16u : 0u;
                int colSafe = (col + 4 <= N) ? col : 0;
                cp16z(bDst + 16u * i, rowp + colSafe, sz);
            }
        }
    };

    load_tile(0, 0);
    asm volatile("cp.async.commit_group;" ::: "memory");
    if (KT > 1) load_tile(1, 1);
    asm volatile("cp.async.commit_group;" ::: "memory");

    const int aWarpRow = wm * 64;
    const int bWarpCol = wn * 32;

    for (int kt = 0; kt < KT; kt++) {
        asm volatile("cp.async.wait_group 1;" ::: "memory");
        __syncthreads();

        if (kt + 2 < KT) load_tile((kt + 2) % NSTAGE, kt + 2);
        asm volatile("cp.async.commit_group;" ::: "memory");

        const int s = kt % NSTAGE;
        const float* As = smem + (size_t)s * A_TILE_F;
        const float* Bs = smem + (size_t)NSTAGE * A_TILE_F + (size_t)s * B_TILE_F;

        #pragma unroll
        for (int kk = 0; kk < 4; kk++) {
            const int kb = kk * 8;
            uint32_t ah[4][4], al[4][4];
            #pragma unroll
            for (int mf = 0; mf < 4; mf++) {
                const float* ap = As + (aWarpRow + mf * 16 + g) * ASTR + kb + t;
                split32(ap[0],            ah[mf][0], al[mf][0]);
                split32(ap[8 * ASTR],     ah[mf][1], al[mf][1]);
                split32(ap[4],            ah[mf][2], al[mf][2]);
                split32(ap[8 * ASTR + 4], ah[mf][3], al[mf][3]);
            }
            uint32_t bh[4][2], bl[4][2];
            #pragma unroll
            for (int nf = 0; nf < 4; nf++) {
                const float* bp = Bs + (kb + t) * BSTR + bWarpCol + nf * 8 + g;
                split32(bp[0],        bh[nf][0], bl[nf][0]);
                split32(bp[4 * BSTR], bh[nf][1], bl[nf][1]);
            }
            // pass 1: Ah*Bh  (16 independent acc tiles between revisits)
            #pragma unroll
            for (int mf = 0; mf < 4; mf++)
                #pragma unroll
                for (int nf = 0; nf < 4; nf++)
                    MMA_TF32(acc[mf][nf], ah[mf], bh[nf]);
            // pass 2: Ah*Bl
            #pragma unroll
            for (int mf = 0; mf < 4; mf++)
                #pragma unroll
                for (int nf = 0; nf < 4; nf++)
                    MMA_TF32(acc[mf][nf], ah[mf], bl[nf]);
            // pass 3: Al*Bh
            #pragma unroll
            for (int mf = 0; mf < 4; mf++)
                #pragma unroll
                for (int nf = 0; nf < 4; nf++)
                    MMA_TF32(acc[mf][nf], al[mf], bh[nf]);
        }
    }

    // ---- epilogue ----
    #pragma unroll
    for (int mf = 0; mf < 4; mf++) {
        const int r0 = m0 + wm * 64 + mf * 16 + g;
        #pragma unroll
        for (int nf = 0; nf < 4; nf++) {
            const int c0 = n0 + wn * 32 + nf * 8 + 2 * t;
            float v0 = acc[mf][nf][0], v1 = acc[mf][nf][1];
            float v2 = acc[mf][nf][2], v3 = acc[mf][nf][3];
            if (bias) {
                if (c0 < N)     { float b = __ldg(bias + c0);     v0 = leaky(v0 + b); v2 = leaky(v2 + b); }
                if (c0 + 1 < N) { float b = __ldg(bias + c0 + 1); v1 = leaky(v1 + b); v3 = leaky(v3 + b); }
            }
            if (r0 < M) {
                if (c0 < N)     C[(size_t)r0 * N + c0]     = v0;
                if (c0 + 1 < N) C[(size_t)r0 * N + c0 + 1] = v1;
            }
            if (r0 + 8 < M) {
                if (c0 < N)     C[(size_t)(r0 + 8) * N + c0]     = v2;
                if (c0 + 1 < N) C[(size_t)(r0 + 8) * N + c0 + 1] = v3;
            }
        }
    }
}

// ===================== non-GEMM kernels (from R1, passing) =====================
__global__ void k_embed(const int* __restrict__ x, const float* __restrict__ emb) {
    int n  = blockIdx.y;
    int j4 = blockIdx.x * blockDim.x + threadIdx.x;
    if (j4 >= F0 / 4) return;
    int col = j4 * 4;
    int t = col / DEMB;
    int d = col % DEMB;
    int tok = x[n * TTOK + t];
    float4 v = *(const float4*)(emb + (size_t)tok * DEMB + d);
    *(float4*)(g_h0 + (size_t)n * F0 + col) = v;
}

__global__ void k_deg_init() {
    int n = blockIdx.x * blockDim.x + threadIdx.x;
    if (n < NNODES) g_deg[n] = 1.0f;
}
__global__ void k_deg_count(const int* __restrict__ dst) {
    int e = blockIdx.x * blockDim.x + threadIdx.x;
    if (e < NEDGES) atomicAdd(&g_deg[dst[e]], 1.0f);
}
__global__ void k_dinv() {
    int n = blockIdx.x * blockDim.x + threadIdx.x;
    if (n < NNODES) g_dinv[n] = rsqrtf(g_deg[n]);
}

__global__ void k_agg_init(const float* __restrict__ xw, float* __restrict__ agg) {
    int n  = blockIdx.y;
    int j4 = blockIdx.x * blockDim.x + threadIdx.x;
    if (j4 >= F1 / 4) return;
    float di = g_dinv[n];
    float s  = di * di;
    float4 v = *(const float4*)(xw + (size_t)n * F1 + j4 * 4);
    v.x *= s; v.y *= s; v.z *= s; v.w *= s;
    *(float4*)(agg + (size_t)n * F1 + j4 * 4) = v;
}

__global__ void k_agg_edges(const float* __restrict__ xw, float* __restrict__ agg,
                            const int* __restrict__ src, const int* __restrict__ dst) {
    int e  = blockIdx.y;
    int j4 = blockIdx.x * blockDim.x + threadIdx.x;
    if (j4 >= F1 / 4) return;
    int s = __ldg(&src[e]);
    int d = __ldg(&dst[e]);
    float nrm = g_dinv[s] * g_dinv[d];
    float4 v = *(const float4*)(xw + (size_t)s * F1 + j4 * 4);
    float* o = agg + (size_t)d * F1 + j4 * 4;
    atomicAdd(o + 0, v.x * nrm);
    atomicAdd(o + 1, v.y * nrm);
    atomicAdd(o + 2, v.z * nrm);
    atomicAdd(o + 3, v.w * nrm);
}

__global__ void k_bias_leaky(float* __restrict__ h, const float* __restrict__ b) {
    int n  = blockIdx.y;
    int j4 = blockIdx.x * blockDim.x + threadIdx.x;
    if (j4 >= F1 / 4) return;
    int c = j4 * 4;
    float4 v  = *(float4*)(h + (size_t)n * F1 + c);
    float4 bb = *(const float4*)(b + c);
    v.x = leaky(v.x + bb.x);
    v.y = leaky(v.y + bb.y);
    v.z = leaky(v.z + bb.z);
    v.w = leaky(v.w + bb.w);
    *(float4*)(h + (size_t)n * F1 + c) = v;
}

__global__ void k_gmax_init() {
    int b  = blockIdx.y;
    int j4 = blockIdx.x * blockDim.x + threadIdx.x;
    if (j4 >= F1 / 4) return;
    unsigned enc_ninf = 0x007FFFFFu;
    uint4 v = make_uint4(enc_ninf, enc_ninf, enc_ninf, enc_ninf);
    *(uint4*)(g_gmax + (size_t)b * F1 + j4 * 4) = v;
}

__global__ void k_gmax(const float* __restrict__ h2, const int* __restrict__ batch) {
    int n  = blockIdx.y;
    int j4 = blockIdx.x * blockDim.x + threadIdx.x;
    if (j4 >= F1 / 4) return;
    int b = __ldg(&batch[n]);
    int c = j4 * 4;
    float4 v = *(const float4*)(h2 + (size_t)n * F1 + c);
    unsigned* o = g_gmax + (size_t)b * F1 + c;
    atomicMax(o + 0, fenc(v.x));
    atomicMax(o + 1, fenc(v.y));
    atomicMax(o + 2, fenc(v.z));
    atomicMax(o + 3, fenc(v.w));
}

__global__ void k_gmax_dec() {
    int b  = blockIdx.y;
    int j4 = blockIdx.x * blockDim.x + threadIdx.x;
    if (j4 >= F1 / 4) return;
    int c = j4 * 4;
    uint4 u = *(const uint4*)(g_gmax + (size_t)b * F1 + c);
    float4 v = make_float4(fdec(u.x), fdec(u.y), fdec(u.z), fdec(u.w));
    *(float4*)(g_g + (size_t)b * F1 + c) = v;
}

__global__ void k_final(const float* __restrict__ g1, const float* __restrict__ Wl2,
                        const float* __restrict__ bl2, float* __restrict__ out) {
    int gwarp = (blockIdx.x * blockDim.x + threadIdx.x) >> 5;
    int lane  = threadIdx.x & 31;
    if (gwarp >= NBATCH * F4) return;
    int m = gwarp >> 2;
    int n = gwarp & 3;
    float acc = 0.0f;
    for (int k = lane; k < F3; k += 32)
        acc = fmaf(g1[(size_t)m * F3 + k], Wl2[(size_t)k * F4 + n], acc);
    #pragma unroll
    for (int o = 16; o > 0; o >>= 1)
        acc += __shfl_xor_sync(0xFFFFFFFFu, acc, o);
    if (lane == 0) out[m * F4 + n] = leaky(acc + bl2[n]);
}

// --------------------------------------------------------------------------
extern "C" void kernel_launch(void* const* d_in, const int* in_sizes, int n_in,
                              void* d_out, int out_size) {
    const int*   x    = (const int*)d_in[0];
    const int*   ei   = (const int*)d_in[1];
    const int*   batch= (const int*)d_in[2];
    const float* emb  = (const float*)d_in[3];
    const float* W1   = (const float*)d_in[4];
    const float* b1   = (const float*)d_in[5];
    const float* W2   = (const float*)d_in[6];
    const float* b2   = (const float*)d_in[7];
    const float* Wl1  = (const float*)d_in[8];
    const float* bl1  = (const float*)d_in[9];
    const float* Wl2  = (const float*)d_in[10];
    const float* bl2  = (const float*)d_in[11];
    float* out = (float*)d_out;

    const int* srcp = ei;
    const int* dstp = ei + NEDGES;

    float *h0, *xw, *agg, *xw2, *gg, *g1;
    cudaGetSymbolAddress((void**)&h0,  g_h0);
    cudaGetSymbolAddress((void**)&xw,  g_xw);
    cudaGetSymbolAddress((void**)&agg, g_agg);
    cudaGetSymbolAddress((void**)&xw2, g_xw2);
    cudaGetSymbolAddress((void**)&gg,  g_g);
    cudaGetSymbolAddress((void**)&g1,  g_g1);

    cudaFuncSetAttribute(k_mma, cudaFuncAttributeMaxDynamicSharedMemorySize, MM_SMEM);

    dim3 blk(256);
    dim3 gEmbed(4, NNODES);
    dim3 gNode6k(6, NNODES);
    dim3 gEdge6k(6, NEDGES);
    dim3 gB6k(6, NBATCH);
    dim3 gGemmBig((F1 + BN - 1) / BN, (NNODES + BM - 1) / BM);  // 47 x 63
    dim3 gGemmL((F3 + BN - 1) / BN, 1);                          // 24 x 1

    // 1. embedding
    k_embed<<<gEmbed, blk>>>(x, emb);
    // 2. degrees -> dinv
    k_deg_init <<<32, 256>>>();
    k_deg_count<<<(NEDGES + 255) / 256, 256>>>(dstp);
    k_dinv     <<<32, 256>>>();
    // 3. conv1 GEMM: xw = h0 @ W1   (3xTF32 mma.sync)
    k_mma<<<gGemmBig, blk, MM_SMEM>>>(h0, W1, nullptr, xw, NNODES, F1, F0);
    // 4. agg1 ; h1 = leaky(agg1 + b1)
    k_agg_init <<<gNode6k, blk>>>(xw, agg);
    k_agg_edges<<<gEdge6k, blk>>>(xw, agg, srcp, dstp);
    k_bias_leaky<<<gNode6k, blk>>>(agg, b1);
    // 5. conv2 GEMM: xw2 = h1 @ W2
    k_mma<<<gGemmBig, blk, MM_SMEM>>>(agg, W2, nullptr, xw2, NNODES, F1, F1);
    // 6. agg2 ; h2 = leaky(agg2 + b2)
    k_agg_init <<<gNode6k, blk>>>(xw2, xw);
    k_agg_edges<<<gEdge6k, blk>>>(xw2, xw, srcp, dstp);
    k_bias_leaky<<<gNode6k, blk>>>(xw, b2);
    // 7. global max pool
    k_gmax_init<<<gB6k, blk>>>();
    k_gmax     <<<gNode6k, blk>>>(xw, batch);
    k_gmax_dec <<<gB6k, blk>>>();
    // 8. lin1 GEMM: g1 = leaky(g @ Wl1 + bl1)
    k_mma<<<gGemmL, blk, MM_SMEM>>>(gg, Wl1, bl1, g1, NBATCH, F3, F1);
    // 9. lin2
    k_final<<<32, 256>>>(g1, Wl2, bl2, out);
}

// round 5
// speedup vs baseline: 1.8004x; 1.2987x over previous
#include <cuda_runtime.h>
#include <cstdint>
#include <cstddef>

// Problem dimensions (fixed by the dataset)
#define NNODES 8000
#define NEDGES 32000
#define NBATCH 64
#define DEMB   200
#define TTOK   20
#define F0     4000   // embed width = conv1 in
#define F1     6000   // conv1/conv2 out
#define F3     3000   // lin1 out
#define F4     4      // lin2 out

// -------- scratch (device globals; no allocation in kernel_launch) --------
__device__ __align__(1024) float    g_h0 [(size_t)NNODES * F0];
__device__ __align__(1024) float    g_xw [(size_t)NNODES * F1];
__device__ __align__(1024) float    g_agg[(size_t)NNODES * F1];
__device__ __align__(1024) float    g_xw2[(size_t)NNODES * F1];
__device__ __align__(1024) float    g_deg [NNODES];
__device__ __align__(1024) float    g_dinv[NNODES];
__device__ __align__(1024) unsigned g_gmax[(size_t)NBATCH * F1];
__device__ __align__(1024) float    g_g   [(size_t)NBATCH * F1];
__device__ __align__(1024) float    g_g1  [(size_t)NBATCH * F3];

__device__ __forceinline__ float leaky(float v) { return v >= 0.0f ? v : 0.01f * v; }

__device__ __forceinline__ unsigned fenc(float f) {
    unsigned u = __float_as_uint(f);
    return (u & 0x80000000u) ? ~u : (u | 0x80000000u);
}
__device__ __forceinline__ float fdec(unsigned u) {
    return (u & 0x80000000u) ? __uint_as_float(u ^ 0x80000000u) : __uint_as_float(~u);
}

// ===================== bf16 mma.sync GEMM with 3xBF16 compensation ================
// C[M,N] = A[M,K] @ B[K,N] ; A row-major, B row-major. Optional bias + leaky epilogue.
// Block tile 128x128, BK=32, 8 warps (2x4), warp tile 64x32, m16n8k16 bf16 (2x tf32 rate).
// Each fp32 operand split: hi = truncate-to-bf16(x) (exact top 16 bits),
// lo = bf16_rn(x - hi).  D += Ah*Bh + Ah*Bl + Al*Bh  -> ~2^-16 relative accuracy.
// 3-stage cp.async pipeline, fp32 tiles in smem, split done at fragment load.

#define BM 128
#define BN 128
#define BK 32
#define ASTR 36      // As row stride (floats), padded
#define BSTR 132     // Bs row stride (floats), padded
#define A_TILE_F (BM * ASTR)
#define B_TILE_F (BK * BSTR)
#define NSTAGE 3
#define MM_SMEM (NSTAGE * (A_TILE_F + B_TILE_F) * 4)   // 105984 bytes

__device__ __forceinline__ void cp16z(uint32_t dst, const void* src, uint32_t srcsize) {
    asm volatile("cp.async.cg.shared.global [%0], [%1], 16, %2;"
                 :: "r"(dst), "l"(src), "r"(srcsize));
}
__device__ __forceinline__ uint32_t smem_u32(const void* p) {
    uint32_t a;
    asm("{ .reg .u64 t; cvta.to.shared.u64 t, %1; cvt.u32.u64 %0, t; }" : "=r"(a) : "l"(p));
    return a;
}

// split a pair of fp32 into packed bf16x2 hi (truncated) and lo (rounded remainder)
__device__ __forceinline__ void split_pack2(float x0, float x1, uint32_t& hi, uint32_t& lo) {
    uint32_t u0 = __float_as_uint(x0), u1 = __float_as_uint(x1);
    uint32_t hp;
    // d = [u0.b2, u0.b3, u1.b2, u1.b3] : lo half = bf16_trunc(x0), hi half = bf16_trunc(x1)
    asm("prmt.b32 %0, %1, %2, 0x7632;" : "=r"(hp) : "r"(u0), "r"(u1));
    float h0 = __uint_as_float(u0 & 0xFFFF0000u);
    float h1 = __uint_as_float(u1 & 0xFFFF0000u);
    float l0 = x0 - h0;
    float l1 = x1 - h1;
    uint32_t lp;
    asm("cvt.rn.bf16x2.f32 %0, %1, %2;" : "=r"(lp) : "f"(l1), "f"(l0));  // hi=bf16(l1), lo=bf16(l0)
    hi = hp; lo = lp;
}

#define MMA_BF16(ACC, AF, BF)                                                      \
    asm volatile(                                                                  \
        "mma.sync.aligned.m16n8k16.row.col.f32.bf16.bf16.f32 "                     \
        "{%0,%1,%2,%3}, {%4,%5,%6,%7}, {%8,%9}, {%0,%1,%2,%3};"                    \
        : "+f"((ACC)[0]), "+f"((ACC)[1]), "+f"((ACC)[2]), "+f"((ACC)[3])           \
        : "r"((AF)[0]), "r"((AF)[1]), "r"((AF)[2]), "r"((AF)[3]),                  \
          "r"((BF)[0]), "r"((BF)[1]))

__global__ void __launch_bounds__(256, 1)
k_mma(const float* __restrict__ A, const float* __restrict__ B,
      const float* __restrict__ bias, float* __restrict__ C,
      int M, int N, int K)
{
    extern __shared__ __align__(16) float smem[];
    const uint32_t sb = smem_u32(smem);

    const int tid  = threadIdx.x;
    const int wid  = tid >> 5;
    const int lane = tid & 31;
    const int g    = lane >> 2;   // group id 0..7
    const int t    = lane & 3;    // thread in group 0..3
    const int wm   = wid >> 2;    // 0..1
    const int wn   = wid & 3;     // 0..3

    const int m0 = blockIdx.y * BM;
    const int n0 = blockIdx.x * BN;
    const int KT = (K + BK - 1) / BK;

    // ---- global load mapping ----
    const int aRow  = tid >> 1;
    const int aColF = (tid & 1) * 16;
    int aRowG = m0 + aRow; if (aRowG > M - 1) aRowG = M - 1;
    const float* aSrcBase = A + (size_t)aRowG * K + aColF;
    const uint32_t aDstBase = sb + (uint32_t)(aRow * ASTR + aColF) * 4u;

    const int bRow  = tid >> 3;              // 0..31 (k within tile)
    const int bColF = (tid & 7) * 16;        // 0..112 (n within tile)
    const uint32_t bDstBase = sb + (uint32_t)(NSTAGE * A_TILE_F) * 4u
                                 + (uint32_t)(bRow * BSTR + bColF) * 4u;

    float acc[4][4][4];
    #pragma unroll
    for (int i = 0; i < 4; i++)
        #pragma unroll
        for (int j = 0; j < 4; j++)
            #pragma unroll
            for (int r = 0; r < 4; r++) acc[i][j][r] = 0.0f;

    auto load_tile = [&](int stage, int kt) {
        const int k0 = kt * BK;
        const uint32_t aDst = aDstBase + (uint32_t)(stage * A_TILE_F) * 4u;
        const uint32_t bDst = bDstBase + (uint32_t)(stage * B_TILE_F) * 4u;
        #pragma unroll
        for (int i = 0; i < 4; i++) {
            int kA = k0 + aColF + 4 * i;
            uint32_t sz = (kA + 4 <= K) ? 16u : 0u;
            cp16z(aDst + 16u * i, aSrcBase + (size_t)k0 + 4 * i, sz);
        }
        {
            const int kB = k0 + bRow;
            const bool krow_ok = (kB < K);
            const float* rowp = B + (size_t)(krow_ok ? kB : 0) * N;
            #pragma unroll
            for (int i = 0; i < 4; i++) {
                int col = n0 + bColF + 4 * i;
                uint32_t sz = (krow_ok && (col + 4 <= N)) ? 16u : 0u;
                int colSafe = (col + 4 <= N) ? col : 0;
                cp16z(bDst + 16u * i, rowp + colSafe, sz);
            }
        }
    };

    load_tile(0, 0);
    asm volatile("cp.async.commit_group;" ::: "memory");
    if (KT > 1) load_tile(1, 1);
    asm volatile("cp.async.commit_group;" ::: "memory");

    const int aWarpRow = wm * 64;
    const int bWarpCol = wn * 32;

    for (int kt = 0; kt < KT; kt++) {
        asm volatile("cp.async.wait_group 1;" ::: "memory");
        __syncthreads();

        if (kt + 2 < KT) load_tile((kt + 2) % NSTAGE, kt + 2);
        asm volatile("cp.async.commit_group;" ::: "memory");

        const int s = kt % NSTAGE;
        const float* As = smem + (size_t)s * A_TILE_F;
        const float* Bs = smem + (size_t)NSTAGE * A_TILE_F + (size_t)s * B_TILE_F;

        #pragma unroll
        for (int kk = 0; kk < 2; kk++) {          // two k16 chunks per BK=32 tile
            const int kb = kk * 16;
            // ---- A fragments: m16n8k16 row-major ----
            // a0={A[g][2t],A[g][2t+1]}  a1={A[g+8][...]}  a2={A[g][2t+8],A[g][2t+9]}  a3={A[g+8][...+8]}
            uint32_t ah[4][4], al[4][4];
            #pragma unroll
            for (int mf = 0; mf < 4; mf++) {
                const float* ap = As + (aWarpRow + mf * 16 + g) * ASTR + kb + 2 * t;
                float2 v0  = *(const float2*)(ap);
                float2 v1  = *(const float2*)(ap + 8 * ASTR);
                float2 v0k = *(const float2*)(ap + 8);
                float2 v1k = *(const float2*)(ap + 8 * ASTR + 8);
                split_pack2(v0.x,  v0.y,  ah[mf][0], al[mf][0]);
                split_pack2(v1.x,  v1.y,  ah[mf][1], al[mf][1]);
                split_pack2(v0k.x, v0k.y, ah[mf][2], al[mf][2]);
                split_pack2(v1k.x, v1k.y, ah[mf][3], al[mf][3]);
            }
            // ---- B fragments: b0={B[2t][n],B[2t+1][n]}  b1={B[2t+8][n],B[2t+9][n]} ----
            uint32_t bh[4][2], bl[4][2];
            #pragma unroll
            for (int nf = 0; nf < 4; nf++) {
                const float* bp = Bs + (kb + 2 * t) * BSTR + bWarpCol + nf * 8 + g;
                float b00 = bp[0];
                float b01 = bp[BSTR];
                float b10 = bp[8 * BSTR];
                float b11 = bp[9 * BSTR];
                split_pack2(b00, b01, bh[nf][0], bl[nf][0]);
                split_pack2(b10, b11, bh[nf][1], bl[nf][1]);
            }
            // pass 1: Ah*Bh  (16 independent acc tiles between revisits)
            #pragma unroll
            for (int mf = 0; mf < 4; mf++)
                #pragma unroll
                for (int nf = 0; nf < 4; nf++)
                    MMA_BF16(acc[mf][nf], ah[mf], bh[nf]);
            // pass 2: Ah*Bl
            #pragma unroll
            for (int mf = 0; mf < 4; mf++)
                #pragma unroll
                for (int nf = 0; nf < 4; nf++)
                    MMA_BF16(acc[mf][nf], ah[mf], bl[nf]);
            // pass 3: Al*Bh
            #pragma unroll
            for (int mf = 0; mf < 4; mf++)
                #pragma unroll
                for (int nf = 0; nf < 4; nf++)
                    MMA_BF16(acc[mf][nf], al[mf], bh[nf]);
        }
    }

    // ---- epilogue ----
    #pragma unroll
    for (int mf = 0; mf < 4; mf++) {
        const int r0 = m0 + wm * 64 + mf * 16 + g;
        #pragma unroll
        for (int nf = 0; nf < 4; nf++) {
            const int c0 = n0 + wn * 32 + nf * 8 + 2 * t;
            float v0 = acc[mf][nf][0], v1 = acc[mf][nf][1];
            float v2 = acc[mf][nf][2], v3 = acc[mf][nf][3];
            if (bias) {
                if (c0 < N)     { float b = __ldg(bias + c0);     v0 = leaky(v0 + b); v2 = leaky(v2 + b); }
                if (c0 + 1 < N) { float b = __ldg(bias + c0 + 1); v1 = leaky(v1 + b); v3 = leaky(v3 + b); }
            }
            if (r0 < M) {
                if (c0 < N)     C[(size_t)r0 * N + c0]     = v0;
                if (c0 + 1 < N) C[(size_t)r0 * N + c0 + 1] = v1;
            }
            if (r0 + 8 < M) {
                if (c0 < N)     C[(size_t)(r0 + 8) * N + c0]     = v2;
                if (c0 + 1 < N) C[(size_t)(r0 + 8) * N + c0 + 1] = v3;
            }
        }
    }
}

// ===================== non-GEMM kernels (passing since R1) =====================
__global__ void k_embed(const int* __restrict__ x, const float* __restrict__ emb) {
    int n  = blockIdx.y;
    int j4 = blockIdx.x * blockDim.x + threadIdx.x;
    if (j4 >= F0 / 4) return;
    int col = j4 * 4;
    int t = col / DEMB;
    int d = col % DEMB;
    int tok = x[n * TTOK + t];
    float4 v = *(const float4*)(emb + (size_t)tok * DEMB + d);
    *(float4*)(g_h0 + (size_t)n * F0 + col) = v;
}

__global__ void k_deg_init() {
    int n = blockIdx.x * blockDim.x + threadIdx.x;
    if (n < NNODES) g_deg[n] = 1.0f;
}
__global__ void k_deg_count(const int* __restrict__ dst) {
    int e = blockIdx.x * blockDim.x + threadIdx.x;
    if (e < NEDGES) atomicAdd(&g_deg[dst[e]], 1.0f);
}
__global__ void k_dinv() {
    int n = blockIdx.x * blockDim.x + threadIdx.x;
    if (n < NNODES) g_dinv[n] = rsqrtf(g_deg[n]);
}

__global__ void k_agg_init(const float* __restrict__ xw, float* __restrict__ agg) {
    int n  = blockIdx.y;
    int j4 = blockIdx.x * blockDim.x + threadIdx.x;
    if (j4 >= F1 / 4) return;
    float di = g_dinv[n];
    float s  = di * di;
    float4 v = *(const float4*)(xw + (size_t)n * F1 + j4 * 4);
    v.x *= s; v.y *= s; v.z *= s; v.w *= s;
    *(float4*)(agg + (size_t)n * F1 + j4 * 4) = v;
}

__global__ void k_agg_edges(const float* __restrict__ xw, float* __restrict__ agg,
                            const int* __restrict__ src, const int* __restrict__ dst) {
    int e  = blockIdx.y;
    int j4 = blockIdx.x * blockDim.x + threadIdx.x;
    if (j4 >= F1 / 4) return;
    int s = __ldg(&src[e]);
    int d = __ldg(&dst[e]);
    float nrm = g_dinv[s] * g_dinv[d];
    float4 v = *(const float4*)(xw + (size_t)s * F1 + j4 * 4);
    float* o = agg + (size_t)d * F1 + j4 * 4;
    atomicAdd(o + 0, v.x * nrm);
    atomicAdd(o + 1, v.y * nrm);
    atomicAdd(o + 2, v.z * nrm);
    atomicAdd(o + 3, v.w * nrm);
}

__global__ void k_bias_leaky(float* __restrict__ h, const float* __restrict__ b) {
    int n  = blockIdx.y;
    int j4 = blockIdx.x * blockDim.x + threadIdx.x;
    if (j4 >= F1 / 4) return;
    int c = j4 * 4;
    float4 v  = *(float4*)(h + (size_t)n * F1 + c);
    float4 bb = *(const float4*)(b + c);
    v.x = leaky(v.x + bb.x);
    v.y = leaky(v.y + bb.y);
    v.z = leaky(v.z + bb.z);
    v.w = leaky(v.w + bb.w);
    *(float4*)(h + (size_t)n * F1 + c) = v;
}

__global__ void k_gmax_init() {
    int b  = blockIdx.y;
    int j4 = blockIdx.x * blockDim.x + threadIdx.x;
    if (j4 >= F1 / 4) return;
    unsigned enc_ninf = 0x007FFFFFu;
    uint4 v = make_uint4(enc_ninf, enc_ninf, enc_ninf, enc_ninf);
    *(uint4*)(g_gmax + (size_t)b * F1 + j4 * 4) = v;
}

__global__ void k_gmax(const float* __restrict__ h2, const int* __restrict__ batch) {
    int n  = blockIdx.y;
    int j4 = blockIdx.x * blockDim.x + threadIdx.x;
    if (j4 >= F1 / 4) return;
    int b = __ldg(&batch[n]);
    int c = j4 * 4;
    float4 v = *(const float4*)(h2 + (size_t)n * F1 + c);
    unsigned* o = g_gmax + (size_t)b * F1 + c;
    atomicMax(o + 0, fenc(v.x));
    atomicMax(o + 1, fenc(v.y));
    atomicMax(o + 2, fenc(v.z));
    atomicMax(o + 3, fenc(v.w));
}

__global__ void k_gmax_dec() {
    int b  = blockIdx.y;
    int j4 = blockIdx.x * blockDim.x + threadIdx.x;
    if (j4 >= F1 / 4) return;
    int c = j4 * 4;
    uint4 u = *(const uint4*)(g_gmax + (size_t)b * F1 + c);
    float4 v = make_float4(fdec(u.x), fdec(u.y), fdec(u.z), fdec(u.w));
    *(float4*)(g_g + (size_t)b * F1 + c) = v;
}

__global__ void k_final(const float* __restrict__ g1, const float* __restrict__ Wl2,
                        const float* __restrict__ bl2, float* __restrict__ out) {
    int gwarp = (blockIdx.x * blockDim.x + threadIdx.x) >> 5;
    int lane  = threadIdx.x & 31;
    if (gwarp >= NBATCH * F4) return;
    int m = gwarp >> 2;
    int n = gwarp & 3;
    float acc = 0.0f;
    for (int k = lane; k < F3; k += 32)
        acc = fmaf(g1[(size_t)m * F3 + k], Wl2[(size_t)k * F4 + n], acc);
    #pragma unroll
    for (int o = 16; o > 0; o >>= 1)
        acc += __shfl_xor_sync(0xFFFFFFFFu, acc, o);
    if (lane == 0) out[m * F4 + n] = leaky(acc + bl2[n]);
}

// --------------------------------------------------------------------------
extern "C" void kernel_launch(void* const* d_in, const int* in_sizes, int n_in,
                              void* d_out, int out_size) {
    const int*   x    = (const int*)d_in[0];
    const int*   ei   = (const int*)d_in[1];
    const int*   batch= (const int*)d_in[2];
    const float* emb  = (const float*)d_in[3];
    const float* W1   = (const float*)d_in[4];
    const float* b1   = (const float*)d_in[5];
    const float* W2   = (const float*)d_in[6];
    const float* b2   = (const float*)d_in[7];
    const float* Wl1  = (const float*)d_in[8];
    const float* bl1  = (const float*)d_in[9];
    const float* Wl2  = (const float*)d_in[10];
    const float* bl2  = (const float*)d_in[11];
    float* out = (float*)d_out;

    const int* srcp = ei;
    const int* dstp = ei + NEDGES;

    float *h0, *xw, *agg, *xw2, *gg, *g1;
    cudaGetSymbolAddress((void**)&h0,  g_h0);
    cudaGetSymbolAddress((void**)&xw,  g_xw);
    cudaGetSymbolAddress((void**)&agg, g_agg);
    cudaGetSymbolAddress((void**)&xw2, g_xw2);
    cudaGetSymbolAddress((void**)&gg,  g_g);
    cudaGetSymbolAddress((void**)&g1,  g_g1);

    cudaFuncSetAttribute(k_mma, cudaFuncAttributeMaxDynamicSharedMemorySize, MM_SMEM);

    dim3 blk(256);
    dim3 gEmbed(4, NNODES);
    dim3 gNode6k(6, NNODES);
    dim3 gEdge6k(6, NEDGES);
    dim3 gB6k(6, NBATCH);
    dim3 gGemmBig((F1 + BN - 1) / BN, (NNODES + BM - 1) / BM);  // 47 x 63
    dim3 gGemmL((F3 + BN - 1) / BN, 1);                          // 24 x 1

    // launch order arranged so the conv1 GEMM lands on ncu's sampled slot (#4)
    // 1. embedding
    k_embed<<<gEmbed, blk>>>(x, emb);
    // 2-3. degrees (dinv computed later; only needed before agg_init)
    k_deg_init <<<32, 256>>>();
    k_deg_count<<<(NEDGES + 255) / 256, 256>>>(dstp);
    // 4. conv1 GEMM: xw = h0 @ W1   (3xBF16 mma.sync)
    k_mma<<<gGemmBig, blk, MM_SMEM>>>(h0, W1, nullptr, xw, NNODES, F1, F0);
    // 5. dinv
    k_dinv<<<32, 256>>>();
    // 6-8. agg1 ; h1 = leaky(agg1 + b1)
    k_agg_init <<<gNode6k, blk>>>(xw, agg);
    k_agg_edges<<<gEdge6k, blk>>>(xw, agg, srcp, dstp);
    k_bias_leaky<<<gNode6k, blk>>>(agg, b1);
    // 9. conv2 GEMM: xw2 = h1 @ W2
    k_mma<<<gGemmBig, blk, MM_SMEM>>>(agg, W2, nullptr, xw2, NNODES, F1, F1);
    // 10-12. agg2 ; h2 = leaky(agg2 + b2)
    k_agg_init <<<gNode6k, blk>>>(xw2, xw);
    k_agg_edges<<<gEdge6k, blk>>>(xw2, xw, srcp, dstp);
    k_bias_leaky<<<gNode6k, blk>>>(xw, b2);
    // 13-15. global max pool
    k_gmax_init<<<gB6k, blk>>>();
    k_gmax     <<<gNode6k, blk>>>(xw, batch);
    k_gmax_dec <<<gB6k, blk>>>();
    // 16. lin1 GEMM: g1 = leaky(g @ Wl1 + bl1)
    k_mma<<<gGemmL, blk, MM_SMEM>>>(gg, Wl1, bl1, g1, NBATCH, F3, F1);
    // 17. lin2
    k_final<<<32, 256>>>(g1, Wl2, bl2, out);
}